// round 8
// baseline (speedup 1.0000x reference)
#include <cuda_runtime.h>
#include <cuda_bf16.h>
#include <cstdint>

#define VOCAB 2048
#define HID   1024
#define TT    256
#define BB    128
#define NCTAS 256          // recurrence CTAs (2 per SM, all resident)

// ---- persistent scratch (static device allocations are allowed) ----
__device__ __align__(128) float         g_YT[(size_t)TT * HID * BB];   // [t][k][m] fp32, 128 MB
__device__ __align__(128) float         g_h0T[HID * BB];               // transposed initial state
__device__ __align__(128) float         g_P[8u * HID * BB];            // k-split partials [g][n][m], 4 MB
__device__ __align__(128) __nv_bfloat16 g_Yhi[(size_t)TT * BB * HID];  // [t*B][k] hi plane, 64 MB
__device__ __align__(128) __nv_bfloat16 g_Ylo[(size_t)TT * BB * HID];  // lo plane, 64 MB
__device__ __align__(128) __nv_bfloat16 g_Bhi[(size_t)VOCAB * HID];    // WdT hi [n][k], 4 MB
__device__ __align__(128) __nv_bfloat16 g_Blo[(size_t)VOCAB * HID];    // WdT lo [n][k], 4 MB
__device__ unsigned g_flags[NCTAS];                                    // per-CTA arrival flags
__device__ unsigned g_phase;                                           // barrier release phase

// ---------------- f32x2 helpers (FFMA2: 2 MACs per issue) ----------------
__device__ __forceinline__ unsigned long long f32x2_pack(float lo, float hi) {
    unsigned long long r;
    asm("mov.b64 %0, {%1, %2};" : "=l"(r) : "f"(lo), "f"(hi));
    return r;
}
__device__ __forceinline__ unsigned long long f32x2_fma(unsigned long long a,
                                                        unsigned long long b,
                                                        unsigned long long c) {
    unsigned long long d;
    asm("fma.rn.f32x2 %0, %1, %2, %3;" : "=l"(d) : "l"(a), "l"(b), "l"(c));
    return d;
}
__device__ __forceinline__ void f32x2_unpack(unsigned long long v, float& lo, float& hi) {
    asm("mov.b64 {%0, %1}, %2;" : "=f"(lo), "=f"(hi) : "l"(v));
}

// ---------------- smem/async helpers ----------------
__device__ __forceinline__ uint32_t smem_u32(const void* p) {
    uint32_t a;
    asm("{ .reg .u64 t; cvta.to.shared.u64 t, %1; cvt.u32.u64 %0, t; }" : "=r"(a) : "l"(p));
    return a;
}
__device__ __forceinline__ void cp_async16(uint32_t sdst, const void* gsrc) {
    asm volatile("cp.async.cg.shared.global [%0], [%1], 16;" :: "r"(sdst), "l"(gsrc));
}
#define CP_COMMIT()  asm volatile("cp.async.commit_group;" ::: "memory")
#define CP_WAIT1()   asm volatile("cp.async.wait_group 1;" ::: "memory")

__device__ __forceinline__ void ldsm_x4(uint32_t r[4], uint32_t addr) {
    asm volatile("ldmatrix.sync.aligned.m8n8.x4.shared.b16 {%0,%1,%2,%3}, [%4];"
                 : "=r"(r[0]), "=r"(r[1]), "=r"(r[2]), "=r"(r[3]) : "r"(addr));
}
__device__ __forceinline__ void mma16816(float d[4], const uint32_t a[4], const uint32_t b0,
                                         const uint32_t b1) {
    asm volatile(
        "mma.sync.aligned.m16n8k16.row.col.f32.bf16.bf16.f32 "
        "{%0,%1,%2,%3}, {%4,%5,%6,%7}, {%8,%9}, {%0,%1,%2,%3};"
        : "+f"(d[0]), "+f"(d[1]), "+f"(d[2]), "+f"(d[3])
        : "r"(a[0]), "r"(a[1]), "r"(a[2]), "r"(a[3]), "r"(b0), "r"(b1));
}

// ---------------- distributed-flag grid barrier (NCTAS CTAs, all resident) ----
// Each CTA release-stores epoch into its own flag slot (no atomic contention).
// CTA0: 256 threads each acquire-spin on one flag, then tid0 publishes g_phase.
// Other CTAs: tid0 acquire-spins on g_phase.
__device__ __forceinline__ void grid_barrier(unsigned epoch) {
    __syncthreads();
    if (blockIdx.x == 0) {
        if (threadIdx.x == 0)
            asm volatile("st.release.gpu.u32 [%0], %1;"
                         :: "l"(&g_flags[0]), "r"(epoch) : "memory");
        unsigned v;
        do {
            asm volatile("ld.acquire.gpu.u32 %0, [%1];"
                         : "=r"(v) : "l"(&g_flags[threadIdx.x]) : "memory");
        } while (v < epoch);
        __syncthreads();
        if (threadIdx.x == 0)
            asm volatile("st.release.gpu.u32 [%0], %1;"
                         :: "l"(&g_phase), "r"(epoch) : "memory");
    } else {
        if (threadIdx.x == 0) {
            asm volatile("st.release.gpu.u32 [%0], %1;"
                         :: "l"(&g_flags[blockIdx.x]), "r"(epoch) : "memory");
            unsigned v;
            do {
                asm volatile("ld.acquire.gpu.u32 %0, [%1];"
                             : "=r"(v) : "l"(&g_phase) : "memory");
                if (v < epoch) __nanosleep(32);
            } while (v < epoch);
        }
    }
    __syncthreads();
}

// ---------------- init: reset barrier + transpose initial state ----------------
__global__ void init_kernel(const float* __restrict__ state) {
    if (blockIdx.x == 0) {
        if (threadIdx.x == 0) g_phase = 0u;
        if (threadIdx.x < NCTAS) g_flags[threadIdx.x] = 0u;
    }
    int idx = blockIdx.x * 256 + threadIdx.x;
    int m = idx & (BB - 1);
    int k = idx >> 7;
    g_h0T[k * BB + m] = state[(size_t)m * HID + k];
}

// ---------------- Wd prep: transpose + bf16 hi/lo split planes ----------------
__global__ void __launch_bounds__(256)
wd_prep(const float* __restrict__ Wd) {
    __shared__ float ts[32][33];
    const int n0 = blockIdx.x * 32, k0 = blockIdx.y * 32;
    const int tx = threadIdx.x & 31, ty = threadIdx.x >> 5;
#pragma unroll
    for (int j = 0; j < 4; j++)
        ts[ty + 8 * j][tx] = Wd[(size_t)(k0 + ty + 8 * j) * VOCAB + n0 + tx];
    __syncthreads();
#pragma unroll
    for (int j = 0; j < 4; j++) {
        float v = ts[tx][ty + 8 * j];
        __nv_bfloat16 h = __float2bfloat16_rn(v);
        __nv_bfloat16 l = __float2bfloat16_rn(v - __bfloat162float(h));
        size_t o = (size_t)(n0 + ty + 8 * j) * HID + k0 + tx;
        g_Bhi[o] = h;
        g_Blo[o] = l;
    }
}

// ---------------- Y prep: YT fp32 [t][k][m] -> Yhi/Ylo bf16 [t*B+m][k] ----------------
__global__ void __launch_bounds__(256)
y_prep() {
    __shared__ float ts[64][33];
    const int t  = blockIdx.z;
    const int k0 = blockIdx.x * 64;
    const int m0 = blockIdx.y * 32;
    const int lane = threadIdx.x & 31, w = threadIdx.x >> 5;
#pragma unroll
    for (int j = 0; j < 8; j++) {
        int kr = w + 8 * j;
        ts[kr][lane] = g_YT[((size_t)t * HID + k0 + kr) * BB + m0 + lane];
    }
    __syncthreads();
#pragma unroll
    for (int j = 0; j < 4; j++) {
        int m = w + 8 * j;
        int kk = lane * 2;
        float v0 = ts[kk][m], v1 = ts[kk + 1][m];
        __nv_bfloat16 h0 = __float2bfloat16_rn(v0);
        __nv_bfloat16 h1 = __float2bfloat16_rn(v1);
        __nv_bfloat16 l0 = __float2bfloat16_rn(v0 - __bfloat162float(h0));
        __nv_bfloat16 l1 = __float2bfloat16_rn(v1 - __bfloat162float(h1));
        size_t o = (size_t)(t * BB + m0 + m) * HID + k0 + kk;
        uint32_t hp = (uint32_t)__bfloat16_as_ushort(h0) | ((uint32_t)__bfloat16_as_ushort(h1) << 16);
        uint32_t lp = (uint32_t)__bfloat16_as_ushort(l0) | ((uint32_t)__bfloat16_as_ushort(l1) << 16);
        *(uint32_t*)&g_Yhi[o] = hp;
        *(uint32_t*)&g_Ylo[o] = lp;
    }
}

// =====================================================================
// Persistent recurrence, 256 CTAs x 256 threads (2 CTAs/SM) — R4-verified.
// CTA (kg 0..7, cg 0..31): k-range kg*128 (full, per thread), cols cg*32.
// 8 partial groups. Thread: 1 m-row x 16 cols x 128 k.
// =====================================================================
__global__ void __launch_bounds__(256, 2)
rnn_persistent(const int*   __restrict__ inputs,   // [B, T]
               const float* __restrict__ Wx,       // [V, H]
               const float* __restrict__ Wh,       // [H, H]
               const float* __restrict__ bias)     // [H]
{
    __shared__ float Whs[128][32];

    const int tid = threadIdx.x;
    const int cta = blockIdx.x;                    // 0..255
    const int cg  = cta & 31;
    const int kg  = cta >> 5;                      // 0..7
    const int n0  = cg * 32;
    const int ks  = kg * 128;

    for (int i = tid; i < 128 * 32; i += 256) {
        int kk = i >> 5, nn = i & 31;
        Whs[kk][nn] = Wh[(size_t)(ks + kk) * HID + n0 + nn];
    }
    __syncthreads();

    const int warp  = tid >> 5;
    const int lane  = tid & 31;
    const int mrow  = (warp & 3) * 32 + lane;
    const int chalf = warp >> 2;                   // 0/1: col half (16 cols)
    const int nc0   = chalf * 16;

    const int nb    = cta * 4 + (warp >> 1);       // phase-B column 0..1023
    const int mhalf = warp & 1;
    const float bv  = bias[nb];

    unsigned epoch = 0;

    for (int t = 0; t < TT; t++) {
        const float* __restrict__ hT =
            (t == 0) ? g_h0T : (g_YT + (size_t)(t - 1) * HID * BB);

        // ---------------- phase A: partial GEMM (128 k x 16 cols per thread) ----------------
        unsigned long long acc[8];
#pragma unroll
        for (int j = 0; j < 8; j++) acc[j] = 0ull;

        const float* __restrict__ hp = hT + (size_t)ks * BB + mrow;

#pragma unroll 16
        for (int k = 0; k < 128; k++) {
            float a = __ldcg(hp + (size_t)k * BB);
            unsigned long long ap = f32x2_pack(a, a);
            const ulonglong2* wr = (const ulonglong2*)&Whs[k][nc0];
            ulonglong2 w0 = wr[0], w1 = wr[1];
            acc[0] = f32x2_fma(ap, w0.x, acc[0]);
            acc[1] = f32x2_fma(ap, w0.y, acc[1]);
            acc[2] = f32x2_fma(ap, w1.x, acc[2]);
            acc[3] = f32x2_fma(ap, w1.y, acc[3]);
            ulonglong2 w2 = wr[2], w3 = wr[3];
            acc[4] = f32x2_fma(ap, w2.x, acc[4]);
            acc[5] = f32x2_fma(ap, w2.y, acc[5]);
            acc[6] = f32x2_fma(ap, w3.x, acc[6]);
            acc[7] = f32x2_fma(ap, w3.y, acc[7]);
        }

        {
            float* pp = g_P + ((size_t)kg * HID + n0 + nc0) * BB + mrow;
#pragma unroll
            for (int q = 0; q < 8; q++) {
                float lo, hi;
                f32x2_unpack(acc[q], lo, hi);
                __stcg(pp + (size_t)(2 * q) * BB, lo);
                __stcg(pp + (size_t)(2 * q + 1) * BB, hi);
            }
        }

        grid_barrier(++epoch);

        // ---------------- phase B: reduce 8 partials + tanh -> YT[t] ----------------
        {
            float* __restrict__ yrow = g_YT + ((size_t)t * HID + nb) * BB;
            const float* __restrict__ prow = g_P + (size_t)nb * BB;
#pragma unroll
            for (int mi = 0; mi < 2; mi++) {
                int m = mhalf * 64 + mi * 32 + lane;
                float s = bv;
#pragma unroll
                for (int gg = 0; gg < 8; gg++)
                    s += __ldcg(prow + (size_t)gg * HID * BB + m);
                int tok = inputs[m * TT + t];
                s += Wx[(size_t)tok * HID + nb];
                __stcg(yrow + m, tanhf(s));
            }
        }

        grid_barrier(++epoch);
    }
}

// =====================================================================
// Decoder on mma.sync bf16 (2-term split: Ah*Bh + Ah*Bl + Al*Bh).
// BM=128, BN=128, BK=64, 256 thr (8 warps, 2m x 4n grid of 64x32 tiles).
// cp.async double-buffered: per stage Ah 16K | Al 16K | Bh 16K | Bl 16K = 64KB.
// =====================================================================
#define DEC_STAGE 65536
#define DEC_SMEM  (2 * DEC_STAGE)

__global__ void __launch_bounds__(256, 1)
decoder_mma(const float* __restrict__ bd, float* __restrict__ out)
{
    extern __shared__ __align__(128) char dsm[];
    const uint32_t sbase = smem_u32(dsm);

    const int tid  = threadIdx.x;
    const int lane = tid & 31;
    const int wid  = tid >> 5;
    const int wm   = wid >> 2;          // 0..1
    const int wn   = wid & 3;           // 0..3
    const int mblk = blockIdx.y;        // 0..255 (= timestep)
    const int n0g  = blockIdx.x * 128;  // global n offset

    const __nv_bfloat16* __restrict__ gAh = g_Yhi + (size_t)mblk * 128 * HID;
    const __nv_bfloat16* __restrict__ gAl = g_Ylo + (size_t)mblk * 128 * HID;
    const __nv_bfloat16* __restrict__ gBh = g_Bhi + (size_t)n0g * HID;
    const __nv_bfloat16* __restrict__ gBl = g_Blo + (size_t)n0g * HID;

    auto issue_stage = [&](int stage, int k0) {
        const uint32_t sb = sbase + stage * DEC_STAGE;
#pragma unroll
        for (int j = 0; j < 4; j++) {
            int c   = tid + 256 * j;
            int row = c >> 3, cx = c & 7;
            uint32_t soff = (uint32_t)(row * 128 + ((cx * 16) ^ ((row & 7) << 4)));
            size_t goff = (size_t)row * HID + k0 + cx * 8;
            cp_async16(sb + soff,         gAh + goff);
            cp_async16(sb + 16384 + soff, gAl + goff);
            cp_async16(sb + 32768 + soff, gBh + goff);
            cp_async16(sb + 49152 + soff, gBl + goff);
        }
    };

    const int roffA = (lane & 7) + ((lane >> 3) & 1) * 8;
    const int kaddA = (lane >> 4) & 1;
    const int roffB = (lane & 7) + ((lane >> 4) & 1) * 8;
    const int kaddB = (lane >> 3) & 1;
    const int swx   = (lane & 7) << 4;
    const uint32_t rowA = (uint32_t)((wm * 64 + roffA) * 128);
    const uint32_t rowB = (uint32_t)((wn * 32 + roffB) * 128);

    float acc[4][4][4];
#pragma unroll
    for (int i = 0; i < 4; i++)
#pragma unroll
        for (int j = 0; j < 4; j++)
#pragma unroll
            for (int q = 0; q < 4; q++) acc[i][j][q] = 0.f;

    issue_stage(0, 0);
    CP_COMMIT();

    for (int it = 0; it < 16; it++) {
        if (it + 1 < 16) issue_stage((it + 1) & 1, (it + 1) * 64);
        CP_COMMIT();
        CP_WAIT1();
        __syncthreads();

        const uint32_t sb = sbase + (it & 1) * DEC_STAGE;
        const uint32_t pAh = sb,          pAl = sb + 16384;
        const uint32_t pBh = sb + 32768,  pBl = sb + 49152;

#pragma unroll
        for (int kk = 0; kk < 4; kk++) {
            const uint32_t kA = (uint32_t)((kk * 32 + kaddA * 16) ^ swx);
            const uint32_t kB = (uint32_t)((kk * 32 + kaddB * 16) ^ swx);

            uint32_t ah[4][4], al[4][4];
#pragma unroll
            for (int mt = 0; mt < 4; mt++) {
                ldsm_x4(ah[mt], pAh + rowA + mt * 2048 + kA);
                ldsm_x4(al[mt], pAl + rowA + mt * 2048 + kA);
            }
            uint32_t bh[2][4], bl[2][4];
#pragma unroll
            for (int np = 0; np < 2; np++) {
                ldsm_x4(bh[np], pBh + rowB + np * 2048 + kB);
                ldsm_x4(bl[np], pBl + rowB + np * 2048 + kB);
            }
#pragma unroll
            for (int mt = 0; mt < 4; mt++) {
#pragma unroll
                for (int nt = 0; nt < 4; nt++) {
                    const int np = nt >> 1, ni = (nt & 1) * 2;
                    mma16816(acc[mt][nt], ah[mt], bh[np][ni], bh[np][ni + 1]);
                    mma16816(acc[mt][nt], ah[mt], bl[np][ni], bl[np][ni + 1]);
                    mma16816(acc[mt][nt], al[mt], bh[np][ni], bh[np][ni + 1]);
                }
            }
        }
        __syncthreads();
    }

    const int rbase = mblk * 128 + wm * 64 + (lane >> 2);
    const int cbase = n0g + wn * 32 + (lane & 3) * 2;
#pragma unroll
    for (int mt = 0; mt < 4; mt++) {
#pragma unroll
        for (int nt = 0; nt < 4; nt++) {
            const int col = cbase + nt * 8;
            const float2 bv = *(const float2*)&bd[col];
            const int r0 = rbase + mt * 16;
            float2 v0 = make_float2(acc[mt][nt][0] + bv.x, acc[mt][nt][1] + bv.y);
            float2 v1 = make_float2(acc[mt][nt][2] + bv.x, acc[mt][nt][3] + bv.y);
            *(float2*)&out[(size_t)r0 * VOCAB + col]       = v0;
            *(float2*)&out[(size_t)(r0 + 8) * VOCAB + col] = v1;
        }
    }
}

// h_final[m][k] = YT[T-1][k][m]
__global__ void copy_hfinal_kernel(float* __restrict__ dst) {
    int idx = blockIdx.x * 256 + threadIdx.x;
    int m = idx & (BB - 1);
    int k = idx >> 7;
    dst[(size_t)m * HID + k] = g_YT[((size_t)(TT - 1) * HID + k) * BB + m];
}

extern "C" void kernel_launch(void* const* d_in, const int* in_sizes, int n_in,
                              void* d_out, int out_size)
{
    const int*   inputs = (const int*)  d_in[0];
    const float* state  = (const float*)d_in[1];
    const float* Wx     = (const float*)d_in[2];
    const float* Wh     = (const float*)d_in[3];
    const float* bias   = (const float*)d_in[4];
    const float* Wd     = (const float*)d_in[5];
    const float* bd     = (const float*)d_in[6];
    float* out = (float*)d_out;

    cudaFuncSetAttribute(decoder_mma, cudaFuncAttributeMaxDynamicSharedMemorySize, DEC_SMEM);

    init_kernel<<<(BB * HID) / 256, 256>>>(state);

    dim3 gridW(VOCAB / 32, HID / 32);
    wd_prep<<<gridW, 256>>>(Wd);

    rnn_persistent<<<NCTAS, 256>>>(inputs, Wx, Wh, bias);

    dim3 gridY(HID / 64, BB / 32, TT);
    y_prep<<<gridY, 256>>>();

    dim3 gridD(VOCAB / 128, TT);   // (16, 256)
    decoder_mma<<<gridD, 256, DEC_SMEM>>>(bd, out);

    size_t hf_off = (size_t)out_size - (size_t)BB * HID;
    copy_hfinal_kernel<<<(BB * HID) / 256, 256>>>(out + hf_off);
}

// round 9
// speedup vs baseline: 1.0326x; 1.0326x over previous
#include <cuda_runtime.h>
#include <cuda_bf16.h>
#include <cstdint>

#define VOCAB 2048
#define HID   1024
#define TT    256
#define BB    128
#define NCTAS 256          // recurrence CTAs (2 per SM, all resident)

// ---- persistent scratch (static device allocations are allowed) ----
__device__ __align__(128) float         g_YT[(size_t)TT * HID * BB];   // [t][k][m] fp32, 128 MB
__device__ __align__(128) float         g_h0T[HID * BB];               // transposed initial state
__device__ __align__(128) float         g_P[8u * HID * BB];            // k-split partials [g][n][m], 4 MB
__device__ __align__(128) __nv_bfloat16 g_Yhi[(size_t)TT * BB * HID];  // [t*B][k] hi plane, 64 MB
__device__ __align__(128) __nv_bfloat16 g_Ylo[(size_t)TT * BB * HID];  // lo plane, 64 MB
__device__ __align__(128) __nv_bfloat16 g_Bhi[(size_t)VOCAB * HID];    // WdT hi [n][k], 4 MB
__device__ __align__(128) __nv_bfloat16 g_Blo[(size_t)VOCAB * HID];    // WdT lo [n][k], 4 MB
__device__ unsigned g_cnt;                                             // barrier arrival counter
__device__ unsigned g_phase;                                           // barrier release phase

// ---------------- f32x2 helpers (FFMA2: 2 MACs per issue) ----------------
__device__ __forceinline__ unsigned long long f32x2_pack(float lo, float hi) {
    unsigned long long r;
    asm("mov.b64 %0, {%1, %2};" : "=l"(r) : "f"(lo), "f"(hi));
    return r;
}
__device__ __forceinline__ unsigned long long f32x2_fma(unsigned long long a,
                                                        unsigned long long b,
                                                        unsigned long long c) {
    unsigned long long d;
    asm("fma.rn.f32x2 %0, %1, %2, %3;" : "=l"(d) : "l"(a), "l"(b), "l"(c));
    return d;
}
__device__ __forceinline__ void f32x2_unpack(unsigned long long v, float& lo, float& hi) {
    asm("mov.b64 {%0, %1}, %2;" : "=f"(lo), "=f"(hi) : "l"(v));
}

// ---------------- smem/async helpers ----------------
__device__ __forceinline__ uint32_t smem_u32(const void* p) {
    uint32_t a;
    asm("{ .reg .u64 t; cvta.to.shared.u64 t, %1; cvt.u32.u64 %0, t; }" : "=r"(a) : "l"(p));
    return a;
}
__device__ __forceinline__ void cp_async16(uint32_t sdst, const void* gsrc) {
    asm volatile("cp.async.cg.shared.global [%0], [%1], 16;" :: "r"(sdst), "l"(gsrc));
}
#define CP_COMMIT()  asm volatile("cp.async.commit_group;" ::: "memory")
#define CP_WAIT1()   asm volatile("cp.async.wait_group 1;" ::: "memory")

__device__ __forceinline__ void ldsm_x4(uint32_t r[4], uint32_t addr) {
    asm volatile("ldmatrix.sync.aligned.m8n8.x4.shared.b16 {%0,%1,%2,%3}, [%4];"
                 : "=r"(r[0]), "=r"(r[1]), "=r"(r[2]), "=r"(r[3]) : "r"(addr));
}
__device__ __forceinline__ void mma16816(float d[4], const uint32_t a[4], const uint32_t b0,
                                         const uint32_t b1) {
    asm volatile(
        "mma.sync.aligned.m16n8k16.row.col.f32.bf16.bf16.f32 "
        "{%0,%1,%2,%3}, {%4,%5,%6,%7}, {%8,%9}, {%0,%1,%2,%3};"
        : "+f"(d[0]), "+f"(d[1]), "+f"(d[2]), "+f"(d[3])
        : "r"(a[0]), "r"(a[1]), "r"(a[2]), "r"(a[3]), "r"(b0), "r"(b1));
}

// ---------------- grid barrier (NCTAS CTAs, all resident) ----------------
__device__ __forceinline__ void grid_barrier(unsigned epoch) {
    __syncthreads();                 // intra-CTA HB; release below publishes all
    if (threadIdx.x == 0) {
        unsigned old;
        asm volatile("atom.add.acq_rel.gpu.u32 %0, [%1], 1;"
                     : "=r"(old) : "l"(&g_cnt) : "memory");
        if (old == epoch * (unsigned)NCTAS - 1u) {
            asm volatile("st.release.gpu.u32 [%0], %1;" :: "l"(&g_phase), "r"(epoch) : "memory");
        } else {
            unsigned cur;
            do {
                asm volatile("ld.acquire.gpu.u32 %0, [%1];" : "=r"(cur) : "l"(&g_phase) : "memory");
                if (cur < epoch) __nanosleep(32);
            } while (cur < epoch);
        }
    }
    __syncthreads();
}

// ---------------- init: reset barrier + transpose initial state ----------------
__global__ void init_kernel(const float* __restrict__ state) {
    if (blockIdx.x == 0 && threadIdx.x == 0) { g_cnt = 0u; g_phase = 0u; }
    int idx = blockIdx.x * 256 + threadIdx.x;
    int m = idx & (BB - 1);
    int k = idx >> 7;
    g_h0T[k * BB + m] = state[(size_t)m * HID + k];
}

// ---------------- dummy: occupies ncu launch slot #3 so rnn_persistent is #4 ----
__global__ void dummy_kernel() { /* deterministic no-op */ }

// ---------------- Wd prep: transpose + bf16 hi/lo split planes ----------------
__global__ void __launch_bounds__(256)
wd_prep(const float* __restrict__ Wd) {
    __shared__ float ts[32][33];
    const int n0 = blockIdx.x * 32, k0 = blockIdx.y * 32;
    const int tx = threadIdx.x & 31, ty = threadIdx.x >> 5;
#pragma unroll
    for (int j = 0; j < 4; j++)
        ts[ty + 8 * j][tx] = Wd[(size_t)(k0 + ty + 8 * j) * VOCAB + n0 + tx];
    __syncthreads();
#pragma unroll
    for (int j = 0; j < 4; j++) {
        float v = ts[tx][ty + 8 * j];
        __nv_bfloat16 h = __float2bfloat16_rn(v);
        __nv_bfloat16 l = __float2bfloat16_rn(v - __bfloat162float(h));
        size_t o = (size_t)(n0 + ty + 8 * j) * HID + k0 + tx;
        g_Bhi[o] = h;
        g_Blo[o] = l;
    }
}

// ---------------- Y prep: YT fp32 [t][k][m] -> Yhi/Ylo bf16 [t*B+m][k] ----------------
__global__ void __launch_bounds__(256)
y_prep() {
    __shared__ float ts[64][33];
    const int t  = blockIdx.z;
    const int k0 = blockIdx.x * 64;
    const int m0 = blockIdx.y * 32;
    const int lane = threadIdx.x & 31, w = threadIdx.x >> 5;
#pragma unroll
    for (int j = 0; j < 8; j++) {
        int kr = w + 8 * j;
        ts[kr][lane] = g_YT[((size_t)t * HID + k0 + kr) * BB + m0 + lane];
    }
    __syncthreads();
#pragma unroll
    for (int j = 0; j < 4; j++) {
        int m = w + 8 * j;
        int kk = lane * 2;
        float v0 = ts[kk][m], v1 = ts[kk + 1][m];
        __nv_bfloat16 h0 = __float2bfloat16_rn(v0);
        __nv_bfloat16 h1 = __float2bfloat16_rn(v1);
        __nv_bfloat16 l0 = __float2bfloat16_rn(v0 - __bfloat162float(h0));
        __nv_bfloat16 l1 = __float2bfloat16_rn(v1 - __bfloat162float(h1));
        size_t o = (size_t)(t * BB + m0 + m) * HID + k0 + kk;
        uint32_t hp = (uint32_t)__bfloat16_as_ushort(h0) | ((uint32_t)__bfloat16_as_ushort(h1) << 16);
        uint32_t lp = (uint32_t)__bfloat16_as_ushort(l0) | ((uint32_t)__bfloat16_as_ushort(l1) << 16);
        *(uint32_t*)&g_Yhi[o] = hp;
        *(uint32_t*)&g_Ylo[o] = lp;
    }
}

// =====================================================================
// Persistent recurrence, 256 CTAs x 256 threads (2 CTAs/SM) — R4-verified.
// CTA (kg 0..7, cg 0..31): k-range kg*128 (full, per thread), cols cg*32.
// 8 partial groups. Thread: 1 m-row x 16 cols x 128 k.
// =====================================================================
__global__ void __launch_bounds__(256, 2)
rnn_persistent(const int*   __restrict__ inputs,   // [B, T]
               const float* __restrict__ Wx,       // [V, H]
               const float* __restrict__ Wh,       // [H, H]
               const float* __restrict__ bias)     // [H]
{
    __shared__ float Whs[128][32];

    const int tid = threadIdx.x;
    const int cta = blockIdx.x;                    // 0..255
    const int cg  = cta & 31;
    const int kg  = cta >> 5;                      // 0..7
    const int n0  = cg * 32;
    const int ks  = kg * 128;

    for (int i = tid; i < 128 * 32; i += 256) {
        int kk = i >> 5, nn = i & 31;
        Whs[kk][nn] = Wh[(size_t)(ks + kk) * HID + n0 + nn];
    }
    __syncthreads();

    const int warp  = tid >> 5;
    const int lane  = tid & 31;
    const int mrow  = (warp & 3) * 32 + lane;
    const int chalf = warp >> 2;                   // 0/1: col half (16 cols)
    const int nc0   = chalf * 16;

    const int nb    = cta * 4 + (warp >> 1);       // phase-B column 0..1023
    const int mhalf = warp & 1;
    const float bv  = bias[nb];

    unsigned epoch = 0;

    for (int t = 0; t < TT; t++) {
        const float* __restrict__ hT =
            (t == 0) ? g_h0T : (g_YT + (size_t)(t - 1) * HID * BB);

        // ---------------- phase A: partial GEMM (128 k x 16 cols per thread) ----------------
        unsigned long long acc[8];
#pragma unroll
        for (int j = 0; j < 8; j++) acc[j] = 0ull;

        const float* __restrict__ hp = hT + (size_t)ks * BB + mrow;

#pragma unroll 8
        for (int k = 0; k < 128; k++) {
            float a = __ldcg(hp + (size_t)k * BB);
            unsigned long long ap = f32x2_pack(a, a);
            const ulonglong2* wr = (const ulonglong2*)&Whs[k][nc0];
            ulonglong2 w0 = wr[0], w1 = wr[1];
            acc[0] = f32x2_fma(ap, w0.x, acc[0]);
            acc[1] = f32x2_fma(ap, w0.y, acc[1]);
            acc[2] = f32x2_fma(ap, w1.x, acc[2]);
            acc[3] = f32x2_fma(ap, w1.y, acc[3]);
            ulonglong2 w2 = wr[2], w3 = wr[3];
            acc[4] = f32x2_fma(ap, w2.x, acc[4]);
            acc[5] = f32x2_fma(ap, w2.y, acc[5]);
            acc[6] = f32x2_fma(ap, w3.x, acc[6]);
            acc[7] = f32x2_fma(ap, w3.y, acc[7]);
        }

        {
            float* pp = g_P + ((size_t)kg * HID + n0 + nc0) * BB + mrow;
#pragma unroll
            for (int q = 0; q < 8; q++) {
                float lo, hi;
                f32x2_unpack(acc[q], lo, hi);
                __stcg(pp + (size_t)(2 * q) * BB, lo);
                __stcg(pp + (size_t)(2 * q + 1) * BB, hi);
            }
        }

        grid_barrier(++epoch);

        // ---------------- phase B: reduce 8 partials + tanh -> YT[t] ----------------
        {
            float* __restrict__ yrow = g_YT + ((size_t)t * HID + nb) * BB;
            const float* __restrict__ prow = g_P + (size_t)nb * BB;
#pragma unroll
            for (int mi = 0; mi < 2; mi++) {
                int m = mhalf * 64 + mi * 32 + lane;
                float s = bv;
#pragma unroll
                for (int gg = 0; gg < 8; gg++)
                    s += __ldcg(prow + (size_t)gg * HID * BB + m);
                int tok = inputs[m * TT + t];
                s += Wx[(size_t)tok * HID + nb];
                __stcg(yrow + m, tanhf(s));
            }
        }

        grid_barrier(++epoch);
    }
}

// =====================================================================
// Decoder on mma.sync bf16 (2-term split: Ah*Bh + Ah*Bl + Al*Bh).
// BM=128, BN=128, BK=64, 256 thr (8 warps, 2m x 4n grid of 64x32 tiles).
// cp.async double-buffered: per stage Ah 16K | Al 16K | Bh 16K | Bl 16K = 64KB.
// =====================================================================
#define DEC_STAGE 65536
#define DEC_SMEM  (2 * DEC_STAGE)

__global__ void __launch_bounds__(256, 1)
decoder_mma(const float* __restrict__ bd, float* __restrict__ out)
{
    extern __shared__ __align__(128) char dsm[];
    const uint32_t sbase = smem_u32(dsm);

    const int tid  = threadIdx.x;
    const int lane = tid & 31;
    const int wid  = tid >> 5;
    const int wm   = wid >> 2;          // 0..1
    const int wn   = wid & 3;           // 0..3
    const int mblk = blockIdx.y;        // 0..255 (= timestep)
    const int n0g  = blockIdx.x * 128;  // global n offset

    const __nv_bfloat16* __restrict__ gAh = g_Yhi + (size_t)mblk * 128 * HID;
    const __nv_bfloat16* __restrict__ gAl = g_Ylo + (size_t)mblk * 128 * HID;
    const __nv_bfloat16* __restrict__ gBh = g_Bhi + (size_t)n0g * HID;
    const __nv_bfloat16* __restrict__ gBl = g_Blo + (size_t)n0g * HID;

    auto issue_stage = [&](int stage, int k0) {
        const uint32_t sb = sbase + stage * DEC_STAGE;
#pragma unroll
        for (int j = 0; j < 4; j++) {
            int c   = tid + 256 * j;
            int row = c >> 3, cx = c & 7;
            uint32_t soff = (uint32_t)(row * 128 + ((cx * 16) ^ ((row & 7) << 4)));
            size_t goff = (size_t)row * HID + k0 + cx * 8;
            cp_async16(sb + soff,         gAh + goff);
            cp_async16(sb + 16384 + soff, gAl + goff);
            cp_async16(sb + 32768 + soff, gBh + goff);
            cp_async16(sb + 49152 + soff, gBl + goff);
        }
    };

    const int roffA = (lane & 7) + ((lane >> 3) & 1) * 8;
    const int kaddA = (lane >> 4) & 1;
    const int roffB = (lane & 7) + ((lane >> 4) & 1) * 8;
    const int kaddB = (lane >> 3) & 1;
    const int swx   = (lane & 7) << 4;
    const uint32_t rowA = (uint32_t)((wm * 64 + roffA) * 128);
    const uint32_t rowB = (uint32_t)((wn * 32 + roffB) * 128);

    float acc[4][4][4];
#pragma unroll
    for (int i = 0; i < 4; i++)
#pragma unroll
        for (int j = 0; j < 4; j++)
#pragma unroll
            for (int q = 0; q < 4; q++) acc[i][j][q] = 0.f;

    issue_stage(0, 0);
    CP_COMMIT();

    for (int it = 0; it < 16; it++) {
        if (it + 1 < 16) issue_stage((it + 1) & 1, (it + 1) * 64);
        CP_COMMIT();
        CP_WAIT1();
        __syncthreads();

        const uint32_t sb = sbase + (it & 1) * DEC_STAGE;
        const uint32_t pAh = sb,          pAl = sb + 16384;
        const uint32_t pBh = sb + 32768,  pBl = sb + 49152;

#pragma unroll
        for (int kk = 0; kk < 4; kk++) {
            const uint32_t kA = (uint32_t)((kk * 32 + kaddA * 16) ^ swx);
            const uint32_t kB = (uint32_t)((kk * 32 + kaddB * 16) ^ swx);

            uint32_t ah[4][4], al[4][4];
#pragma unroll
            for (int mt = 0; mt < 4; mt++) {
                ldsm_x4(ah[mt], pAh + rowA + mt * 2048 + kA);
                ldsm_x4(al[mt], pAl + rowA + mt * 2048 + kA);
            }
            uint32_t bh[2][4], bl[2][4];
#pragma unroll
            for (int np = 0; np < 2; np++) {
                ldsm_x4(bh[np], pBh + rowB + np * 2048 + kB);
                ldsm_x4(bl[np], pBl + rowB + np * 2048 + kB);
            }
#pragma unroll
            for (int mt = 0; mt < 4; mt++) {
#pragma unroll
                for (int nt = 0; nt < 4; nt++) {
                    const int np = nt >> 1, ni = (nt & 1) * 2;
                    mma16816(acc[mt][nt], ah[mt], bh[np][ni], bh[np][ni + 1]);
                    mma16816(acc[mt][nt], ah[mt], bl[np][ni], bl[np][ni + 1]);
                    mma16816(acc[mt][nt], al[mt], bh[np][ni], bh[np][ni + 1]);
                }
            }
        }
        __syncthreads();
    }

    const int rbase = mblk * 128 + wm * 64 + (lane >> 2);
    const int cbase = n0g + wn * 32 + (lane & 3) * 2;
#pragma unroll
    for (int mt = 0; mt < 4; mt++) {
#pragma unroll
        for (int nt = 0; nt < 4; nt++) {
            const int col = cbase + nt * 8;
            const float2 bv = *(const float2*)&bd[col];
            const int r0 = rbase + mt * 16;
            float2 v0 = make_float2(acc[mt][nt][0] + bv.x, acc[mt][nt][1] + bv.y);
            float2 v1 = make_float2(acc[mt][nt][2] + bv.x, acc[mt][nt][3] + bv.y);
            *(float2*)&out[(size_t)r0 * VOCAB + col]       = v0;
            *(float2*)&out[(size_t)(r0 + 8) * VOCAB + col] = v1;
        }
    }
}

// h_final[m][k] = YT[T-1][k][m]
__global__ void copy_hfinal_kernel(float* __restrict__ dst) {
    int idx = blockIdx.x * 256 + threadIdx.x;
    int m = idx & (BB - 1);
    int k = idx >> 7;
    dst[(size_t)m * HID + k] = g_YT[((size_t)(TT - 1) * HID + k) * BB + m];
}

extern "C" void kernel_launch(void* const* d_in, const int* in_sizes, int n_in,
                              void* d_out, int out_size)
{
    const int*   inputs = (const int*)  d_in[0];
    const float* state  = (const float*)d_in[1];
    const float* Wx     = (const float*)d_in[2];
    const float* Wh     = (const float*)d_in[3];
    const float* bias   = (const float*)d_in[4];
    const float* Wd     = (const float*)d_in[5];
    const float* bd     = (const float*)d_in[6];
    float* out = (float*)d_out;

    cudaFuncSetAttribute(decoder_mma, cudaFuncAttributeMaxDynamicSharedMemorySize, DEC_SMEM);

    // launch #1
    init_kernel<<<(BB * HID) / 256, 256>>>(state);

    // launch #2
    dim3 gridW(VOCAB / 32, HID / 32);
    wd_prep<<<gridW, 256>>>(Wd);

    // launch #3 — positions rnn_persistent at ncu's sampled slot (#4)
    dummy_kernel<<<1, 32>>>();

    // launch #4 — the kernel we need profiled
    rnn_persistent<<<NCTAS, 256>>>(inputs, Wx, Wh, bias);

    // launch #5
    dim3 gridY(HID / 64, BB / 32, TT);
    y_prep<<<gridY, 256>>>();

    // launch #6
    dim3 gridD(VOCAB / 128, TT);   // (16, 256)
    decoder_mma<<<gridD, 256, DEC_SMEM>>>(bd, out);

    // launch #7
    size_t hf_off = (size_t)out_size - (size_t)BB * HID;
    copy_hfinal_kernel<<<(BB * HID) / 256, 256>>>(out + hf_off);
}